// round 6
// baseline (speedup 1.0000x reference)
#include <cuda_runtime.h>

// GlobalNHC: Nose-Hoover chain thermostat, B=32, N=131072, D=3, C=5, NRESPA=2 x 7 SY.
// Persistent kernel, 256 blocks x 512 threads (2 CTAs/SM):
//   phase1: coalesced float4 KE reduction, 6-deep load batches, 2 accumulators
//   prefetch first phase-3 batch -> grid spin-sync + chain (thread 0) overlap
//   phase3: coalesced rescale from L2-hot lines, streaming stores.
//
// mom enters the integrator only via KE = sum(mom^2/mas) and a uniform per-batch
// rescale, so the 14 substeps collapse to scalar chain math with KE *= s^2.

#define BB     32
#define NATM   131072
#define DDIM   3
#define CCH    5
#define NPER   (NATM * DDIM)        // 393216 floats per batch
#define NVEC   (NPER / 4)           // 98304 float4 per batch
#define GX     8                    // blocks per batch
#define NBLK   (GX * BB)            // 256 blocks (2 CTAs/SM)
#define TPB    512
#define V4PB   (NVEC / GX)          // 12288 float4 per block
#define V4PT   (V4PB / TPB)         // 24 float4 per thread
#define BAT    6                    // load batch depth (24 regs)
#define NBAT   (V4PT / BAT)         // 4 batches
#define NRESPA_ 2

__device__ double       g_part[NBLK];       // per-block KE partials
__device__ unsigned int g_bar;              // monotonic arrival counter (never reset)

__device__ __forceinline__ void st_stream(float4* p, float4 v) {
    asm volatile("st.global.cs.v4.f32 [%0], {%1,%2,%3,%4};"
                 :: "l"(p), "f"(v.x), "f"(v.y), "f"(v.z), "f"(v.w) : "memory");
}

__global__ void __launch_bounds__(TPB, 2)
nhc_fused_kernel(const float4* __restrict__ mom4,
                 const float*  __restrict__ mas,
                 const float*  __restrict__ kbt,
                 const float*  __restrict__ dtm,
                 const float*  __restrict__ pos_nhc,
                 const float*  __restrict__ mom_nhc,
                 const float*  __restrict__ mas_nhc,
                 const float*  __restrict__ stp_p,
                 float4* __restrict__ out_mom4,
                 float*  __restrict__ out_posnhc,
                 float*  __restrict__ out_momnhc) {
    const int gx = blockIdx.x;                 // 0..GX-1
    const int b  = blockIdx.y;                 // batch
    const int t  = threadIdx.x;

    const float4* m    = mom4 + (size_t)b * NVEC;
    const float*  masb = mas  + (size_t)b * NATM;
    const int vbase = gx * V4PB;

    // ---------------- Phase 1: KE partial, coalesced, 6-deep batches -------
    // float4 at index L covers elements E=4L..4L+3; atom a=E/3, r=E%3 splits
    // the 4 squares between atoms a and a+1.
    float acc0 = 0.0f, acc1 = 0.0f;
    #pragma unroll
    for (int kb = 0; kb < NBAT; kb++) {
        float4 buf[BAT];
        #pragma unroll
        for (int j = 0; j < BAT; j++)
            buf[j] = m[vbase + (kb * BAT + j) * TPB + t];
        #pragma unroll
        for (int j = 0; j < BAT; j++) {
            const unsigned L = (unsigned)(vbase + (kb * BAT + j) * TPB + t);
            const unsigned E = 4u * L;
            const unsigned a = __umulhi(E, 0xAAAAAAABu) >> 1;   // E/3
            const unsigned r = E - 3u * a;                      // E%3
            float4 v = buf[j];
            float p  = v.x * v.x, q  = v.y * v.y;
            float u  = v.z * v.z, w2 = v.w * v.w;
            float cA = p, cB = w2;
            if (r < 2u)  cA += q; else cB += q;
            if (r == 0u) cA += u; else cB += u;
            acc0 += __fdividef(cA, masb[a]);
            acc1 += __fdividef(cB, masb[a + 1]);
        }
    }
    float acc = acc0 + acc1;

    // warp reduce (float), then cross-warp in double
    #pragma unroll
    for (int off = 16; off > 0; off >>= 1)
        acc += __shfl_down_sync(0xffffffffu, acc, off);

    __shared__ double s_warp[TPB / 32];
    __shared__ float  s_scale;
    const int wid = t >> 5, lid = t & 31;
    if (lid == 0) s_warp[wid] = (double)acc;
    __syncthreads();

    // -------- Prefetch first phase-3 batch (hides sync + chain latency) ----
    float4 pre[BAT];
    #pragma unroll
    for (int j = 0; j < BAT; j++)
        pre[j] = m[vbase + j * TPB + t];

    if (t == 0) {
        double tot = 0.0;
        #pragma unroll
        for (int i = 0; i < TPB / 32; i++) tot += s_warp[i];
        g_part[b * GX + gx] = tot;
        __threadfence();

        // ---------------- Grid sync (ticketed, replay-safe) ----------------
        unsigned int ticket = atomicAdd(&g_bar, 1u);
        unsigned int target = (ticket / NBLK + 1u) * NBLK;
        while (*((volatile unsigned int*)&g_bar) < target) __nanosleep(20);
        __threadfence();

        // ---------------- Phase 2: chain math for batch b ----------------
        double ked = 0.0;
        #pragma unroll
        for (int i = 0; i < GX; i++) ked += g_part[b * GX + i];

        const float wts[7] = {
            0.78451361047756f, 0.235573213359357f, -1.17767998417887f,
            (float)(1.0 - 2.0 * (0.78451361047756 + 0.235573213359357 - 1.17767998417887)),
            -1.17767998417887f, 0.235573213359357f, 0.78451361047756f
        };

        const double kgd = (double)kbt[b] * (double)(NATM * DDIM);
        const float  kbT = kbt[b];
        const float  dts = dtm[b] * (stp_p[0] / (float)NRESPA_);

        float pn[CCH], mn[CCH], imq[CCH];
        #pragma unroll
        for (int c = 0; c < CCH; c++) {
            pn[c]  = pos_nhc[b * CCH + c];
            mn[c]  = mom_nhc[b * CCH + c];
            imq[c] = 1.0f / mas_nhc[b * CCH + c];
        }

        double cum = 1.0;
        for (int r = 0; r < NRESPA_; r++) {
            #pragma unroll
            for (int iw = 0; iw < 7; iw++) {
                const float dea  = dts * wts[iw];
                const float dea2 = dea * 0.5f;
                const float dea4 = dea * 0.25f;

                float g[CCH], mc[CCH];
                g[0] = (float)(ked - kgd);
                #pragma unroll
                for (int j = 1; j < CCH; j++)
                    g[j] = mn[j - 1] * mn[j - 1] * imq[j - 1] - kbT;

                #pragma unroll
                for (int c = 0; c < CCH; c++) mc[c] = mn[c];
                mc[CCH - 1] += g[CCH - 1] * dea2;

                #pragma unroll
                for (int j = CCH - 2; j >= 0; j--) {
                    float f = __expf(-mc[j + 1] * imq[j + 1] * dea4);
                    mc[j] = (mc[j] * f + g[j] * dea2) * f;
                }

                #pragma unroll
                for (int c = 0; c < CCH; c++) pn[c] += mc[c] * imq[c] * dea;

                const float s = __expf(-mc[0] * imq[0] * dea);
                cum *= (double)s;
                ked *= (double)s * (double)s;

                g[0] = (float)(ked - kgd);
                #pragma unroll
                for (int j = CCH - 2; j >= 0; j--) {
                    float f = __expf(-mc[j + 1] * imq[j + 1] * dea4);
                    mc[j] = (mc[j] * f + g[j] * dea2) * f;
                }
                mc[CCH - 1] += g[CCH - 1] * dea2;

                #pragma unroll
                for (int c = 0; c < CCH; c++) mn[c] = mc[c];
            }
        }

        s_scale = (float)cum;
        if (gx == 0) {
            #pragma unroll
            for (int c = 0; c < CCH; c++) {
                out_posnhc[b * CCH + c] = pn[c];
                out_momnhc[b * CCH + c] = mn[c];
            }
        }
    }
    __syncthreads();

    // ------- Phase 3: rescale, coalesced (L2-hot reads, st.cs writes) ------
    const float s = s_scale;
    float4* o = out_mom4 + (size_t)b * NVEC;

    // batch 0 from prefetched registers
    #pragma unroll
    for (int j = 0; j < BAT; j++) {
        float4 v = pre[j];
        v.x *= s; v.y *= s; v.z *= s; v.w *= s;
        st_stream(o + vbase + j * TPB + t, v);
    }
    // remaining batches
    #pragma unroll
    for (int kb = 1; kb < NBAT; kb++) {
        float4 buf[BAT];
        #pragma unroll
        for (int j = 0; j < BAT; j++)
            buf[j] = m[vbase + (kb * BAT + j) * TPB + t];
        #pragma unroll
        for (int j = 0; j < BAT; j++) {
            float4 v = buf[j];
            v.x *= s; v.y *= s; v.z *= s; v.w *= s;
            st_stream(o + vbase + (kb * BAT + j) * TPB + t, v);
        }
    }
}

// ---------------------------------------------------------------------------
extern "C" void kernel_launch(void* const* d_in, const int* in_sizes, int n_in,
                              void* d_out, int out_size) {
    // inputs: 0 pos, 1 mom, 2 mas, 3 kbt, 4 dtm, 5 pos_nhc, 6 mom_nhc, 7 mas_nhc, 8 stp
    const float* mom     = (const float*)d_in[1];
    const float* mas     = (const float*)d_in[2];
    const float* kbt     = (const float*)d_in[3];
    const float* dtm     = (const float*)d_in[4];
    const float* pos_nhc = (const float*)d_in[5];
    const float* mom_nhc = (const float*)d_in[6];
    const float* mas_nhc = (const float*)d_in[7];
    const float* stp     = (const float*)d_in[8];

    float* out = (float*)d_out;
    float* out_mom    = out;                          // [B, N, D]
    float* out_posnhc = out + (size_t)BB * NPER;      // [B, C]
    float* out_momnhc = out_posnhc + BB * CCH;        // [B, C]

    dim3 grid(GX, BB);                                // 256 blocks, 2 per SM
    nhc_fused_kernel<<<grid, TPB>>>(
        (const float4*)mom, mas,
        kbt, dtm, pos_nhc, mom_nhc, mas_nhc, stp,
        (float4*)out_mom, out_posnhc, out_momnhc);
}

// round 7
// speedup vs baseline: 1.0421x; 1.0421x over previous
#include <cuda_runtime.h>

// GlobalNHC: Nose-Hoover chain thermostat, B=32, N=131072, D=3, C=5, NRESPA=2 x 7 SY.
// Persistent kernel, 128 blocks x 1024 threads (1 CTA/SM — this exact shape keeps
// the mom/mas working set L2-resident across graph replays; do not perturb):
//   phase1: coalesced float4 KE reduction, 8-deep load batches
//   smem-stage first 2 phase-3 float4s -> grid spin-sync + chain (thread 0) overlap
//   phase3: coalesced rescale from L2-hot lines, streaming stores.
//
// mom enters the integrator only via KE = sum(mom^2/mas) and a uniform per-batch
// rescale, so the 14 substeps collapse to scalar chain math with KE *= s^2.

#define BB     32
#define NATM   131072
#define DDIM   3
#define CCH    5
#define NPER   (NATM * DDIM)        // 393216 floats per batch
#define NVEC   (NPER / 4)           // 98304 float4 per batch
#define GX     4                    // blocks per batch
#define NBLK   (GX * BB)            // 128 blocks total (1 CTA/SM, all resident)
#define TPB    1024
#define V4PB   (NVEC / GX)          // 24576 float4 per block
#define V4PT   (V4PB / TPB)         // 24 float4 per thread
#define PRE    2                    // float4s staged in smem before the sync
#define NRESPA_ 2

__device__ double       g_part[NBLK];       // per-block KE partials
__device__ unsigned int g_bar;              // monotonic arrival counter (never reset)

__device__ __forceinline__ void st_stream(float4* p, float4 v) {
    asm volatile("st.global.cs.v4.f32 [%0], {%1,%2,%3,%4};"
                 :: "l"(p), "f"(v.x), "f"(v.y), "f"(v.z), "f"(v.w) : "memory");
}

__global__ void __launch_bounds__(TPB, 1)
nhc_fused_kernel(const float4* __restrict__ mom4,
                 const float*  __restrict__ mas,
                 const float*  __restrict__ kbt,
                 const float*  __restrict__ dtm,
                 const float*  __restrict__ pos_nhc,
                 const float*  __restrict__ mom_nhc,
                 const float*  __restrict__ mas_nhc,
                 const float*  __restrict__ stp_p,
                 float4* __restrict__ out_mom4,
                 float*  __restrict__ out_posnhc,
                 float*  __restrict__ out_momnhc) {
    const int gx = blockIdx.x;                 // 0..GX-1
    const int b  = blockIdx.y;                 // batch
    const int t  = threadIdx.x;

    const float4* m    = mom4 + (size_t)b * NVEC;
    const float*  masb = mas  + (size_t)b * NATM;
    const int vbase = gx * V4PB;

    // ---------------- Phase 1: KE partial, coalesced, 8-deep batches -------
    // float4 at index L covers elements E=4L..4L+3; atom a=E/3, r=E%3 splits
    // the 4 squares between atoms a and a+1.
    float acc0 = 0.0f, acc1 = 0.0f;
    #pragma unroll
    for (int kb = 0; kb < 3; kb++) {
        float4 buf[8];
        #pragma unroll
        for (int j = 0; j < 8; j++)
            buf[j] = m[vbase + (kb * 8 + j) * TPB + t];
        #pragma unroll
        for (int j = 0; j < 8; j++) {
            const unsigned L = (unsigned)(vbase + (kb * 8 + j) * TPB + t);
            const unsigned E = 4u * L;
            const unsigned a = __umulhi(E, 0xAAAAAAABu) >> 1;   // E/3
            const unsigned r = E - 3u * a;                      // E%3
            float4 v = buf[j];
            float p  = v.x * v.x, q  = v.y * v.y;
            float u  = v.z * v.z, w2 = v.w * v.w;
            float cA = p, cB = w2;
            if (r < 2u)  cA += q; else cB += q;
            if (r == 0u) cA += u; else cB += u;
            acc0 += __fdividef(cA, masb[a]);
            acc1 += __fdividef(cB, masb[a + 1]);
        }
    }
    float acc = acc0 + acc1;

    // warp reduce (float), then cross-warp in double
    #pragma unroll
    for (int off = 16; off > 0; off >>= 1)
        acc += __shfl_down_sync(0xffffffffu, acc, off);

    __shared__ double s_warp[TPB / 32];
    __shared__ float  s_scale;
    __shared__ float4 s_stage[PRE * TPB];   // 32 KB staging buffer
    const int wid = t >> 5, lid = t & 31;
    if (lid == 0) s_warp[wid] = (double)acc;
    __syncthreads();

    // ---- Stage first PRE phase-3 float4s in smem (overlaps chain/sync) ----
    // Each thread later reads back only its own slots, so the existing
    // __syncthreads below is sufficient ordering.
    #pragma unroll
    for (int j = 0; j < PRE; j++)
        s_stage[j * TPB + t] = m[vbase + j * TPB + t];

    if (t == 0) {
        double tot = 0.0;
        #pragma unroll
        for (int i = 0; i < TPB / 32; i++) tot += s_warp[i];
        g_part[b * GX + gx] = tot;
        __threadfence();

        // ---------------- Grid sync (ticketed, replay-safe) ----------------
        unsigned int ticket = atomicAdd(&g_bar, 1u);
        unsigned int target = (ticket / NBLK + 1u) * NBLK;
        while (*((volatile unsigned int*)&g_bar) < target) __nanosleep(32);
        __threadfence();

        // ---------------- Phase 2: chain math for batch b ----------------
        double ked = 0.0;
        #pragma unroll
        for (int i = 0; i < GX; i++) ked += g_part[b * GX + i];

        const float wts[7] = {
            0.78451361047756f, 0.235573213359357f, -1.17767998417887f,
            (float)(1.0 - 2.0 * (0.78451361047756 + 0.235573213359357 - 1.17767998417887)),
            -1.17767998417887f, 0.235573213359357f, 0.78451361047756f
        };

        const double kgd = (double)kbt[b] * (double)(NATM * DDIM);
        const float  kbT = kbt[b];
        const float  dts = dtm[b] * (stp_p[0] / (float)NRESPA_);

        float pn[CCH], mn[CCH], imq[CCH];
        #pragma unroll
        for (int c = 0; c < CCH; c++) {
            pn[c]  = pos_nhc[b * CCH + c];
            mn[c]  = mom_nhc[b * CCH + c];
            imq[c] = 1.0f / mas_nhc[b * CCH + c];
        }

        double cum = 1.0;
        for (int r = 0; r < NRESPA_; r++) {
            #pragma unroll
            for (int iw = 0; iw < 7; iw++) {
                const float dea  = dts * wts[iw];
                const float dea2 = dea * 0.5f;
                const float dea4 = dea * 0.25f;

                float g[CCH], mc[CCH];
                g[0] = (float)(ked - kgd);
                #pragma unroll
                for (int j = 1; j < CCH; j++)
                    g[j] = mn[j - 1] * mn[j - 1] * imq[j - 1] - kbT;

                #pragma unroll
                for (int c = 0; c < CCH; c++) mc[c] = mn[c];
                mc[CCH - 1] += g[CCH - 1] * dea2;

                #pragma unroll
                for (int j = CCH - 2; j >= 0; j--) {
                    float f = __expf(-mc[j + 1] * imq[j + 1] * dea4);
                    mc[j] = (mc[j] * f + g[j] * dea2) * f;
                }

                #pragma unroll
                for (int c = 0; c < CCH; c++) pn[c] += mc[c] * imq[c] * dea;

                const float s = __expf(-mc[0] * imq[0] * dea);
                cum *= (double)s;
                ked *= (double)s * (double)s;

                g[0] = (float)(ked - kgd);
                #pragma unroll
                for (int j = CCH - 2; j >= 0; j--) {
                    float f = __expf(-mc[j + 1] * imq[j + 1] * dea4);
                    mc[j] = (mc[j] * f + g[j] * dea2) * f;
                }
                mc[CCH - 1] += g[CCH - 1] * dea2;

                #pragma unroll
                for (int c = 0; c < CCH; c++) mn[c] = mc[c];
            }
        }

        s_scale = (float)cum;
        if (gx == 0) {
            #pragma unroll
            for (int c = 0; c < CCH; c++) {
                out_posnhc[b * CCH + c] = pn[c];
                out_momnhc[b * CCH + c] = mn[c];
            }
        }
    }
    __syncthreads();

    // ------- Phase 3: rescale, coalesced (L2-hot reads, st.cs writes) ------
    const float s = s_scale;
    float4* o = out_mom4 + (size_t)b * NVEC;

    // staged float4s first (already on-chip)
    #pragma unroll
    for (int j = 0; j < PRE; j++) {
        float4 v = s_stage[j * TPB + t];
        v.x *= s; v.y *= s; v.z *= s; v.w *= s;
        st_stream(o + vbase + j * TPB + t, v);
    }
    // remaining 22 float4s: batches of 8, 8, 6
    #pragma unroll
    for (int kb = 0; kb < 3; kb++) {
        const int depth = (kb < 2) ? 8 : 6;
        float4 buf[8];
        #pragma unroll
        for (int j = 0; j < 8; j++) {
            if (j < depth)
                buf[j] = m[vbase + (PRE + kb * 8 + j) * TPB + t];
        }
        #pragma unroll
        for (int j = 0; j < 8; j++) {
            if (j < depth) {
                float4 v = buf[j];
                v.x *= s; v.y *= s; v.z *= s; v.w *= s;
                st_stream(o + vbase + (PRE + kb * 8 + j) * TPB + t, v);
            }
        }
    }
}

// ---------------------------------------------------------------------------
extern "C" void kernel_launch(void* const* d_in, const int* in_sizes, int n_in,
                              void* d_out, int out_size) {
    // inputs: 0 pos, 1 mom, 2 mas, 3 kbt, 4 dtm, 5 pos_nhc, 6 mom_nhc, 7 mas_nhc, 8 stp
    const float* mom     = (const float*)d_in[1];
    const float* mas     = (const float*)d_in[2];
    const float* kbt     = (const float*)d_in[3];
    const float* dtm     = (const float*)d_in[4];
    const float* pos_nhc = (const float*)d_in[5];
    const float* mom_nhc = (const float*)d_in[6];
    const float* mas_nhc = (const float*)d_in[7];
    const float* stp     = (const float*)d_in[8];

    float* out = (float*)d_out;
    float* out_mom    = out;                          // [B, N, D]
    float* out_posnhc = out + (size_t)BB * NPER;      // [B, C]
    float* out_momnhc = out_posnhc + BB * CCH;        // [B, C]

    dim3 grid(GX, BB);                                // 128 blocks, 1 per SM
    nhc_fused_kernel<<<grid, TPB>>>(
        (const float4*)mom, mas,
        kbt, dtm, pos_nhc, mom_nhc, mas_nhc, stp,
        (float4*)out_mom, out_posnhc, out_momnhc);
}

// round 8
// speedup vs baseline: 1.8384x; 1.7642x over previous
#include <cuda_runtime.h>

// GlobalNHC: Nose-Hoover chain thermostat, B=32, N=131072, D=3, C=5, NRESPA=2 x 7 SY.
// Persistent kernel, 128 blocks x 1024 threads (1 CTA/SM). R5 structure, plus:
// 192 KB dynamic smem stages the first 12/24 float4s per thread during phase 1,
// so half of phase 3 reads from smem (deterministic on-chip) instead of L2.
//
// mom enters the integrator only via KE = sum(mom^2/mas) and a uniform per-batch
// rescale, so the 14 substeps collapse to scalar chain math with KE *= s^2.

#define BB     32
#define NATM   131072
#define DDIM   3
#define CCH    5
#define NPER   (NATM * DDIM)        // 393216 floats per batch
#define NVEC   (NPER / 4)           // 98304 float4 per batch
#define GX     4                    // blocks per batch
#define NBLK   (GX * BB)            // 128 blocks total (1 CTA/SM, all resident)
#define TPB    1024
#define V4PB   (NVEC / GX)          // 24576 float4 per block
#define V4PT   (V4PB / TPB)         // 24 float4 per thread
#define SSTG   12                   // float4s per thread staged in smem
#define SMEM_DYN (SSTG * TPB * 16)  // 196608 B
#define NRESPA_ 2

__device__ double       g_part[NBLK];       // per-block KE partials
__device__ unsigned int g_bar;              // monotonic arrival counter (never reset)

__device__ __forceinline__ void st_stream(float4* p, float4 v) {
    asm volatile("st.global.cs.v4.f32 [%0], {%1,%2,%3,%4};"
                 :: "l"(p), "f"(v.x), "f"(v.y), "f"(v.z), "f"(v.w) : "memory");
}

__global__ void __launch_bounds__(TPB, 1)
nhc_fused_kernel(const float4* __restrict__ mom4,
                 const float*  __restrict__ mas,
                 const float*  __restrict__ kbt,
                 const float*  __restrict__ dtm,
                 const float*  __restrict__ pos_nhc,
                 const float*  __restrict__ mom_nhc,
                 const float*  __restrict__ mas_nhc,
                 const float*  __restrict__ stp_p,
                 float4* __restrict__ out_mom4,
                 float*  __restrict__ out_posnhc,
                 float*  __restrict__ out_momnhc) {
    extern __shared__ float4 s_stage[];        // SSTG * TPB float4s
    const int gx = blockIdx.x;                 // 0..GX-1
    const int b  = blockIdx.y;                 // batch
    const int t  = threadIdx.x;

    const float4* m    = mom4 + (size_t)b * NVEC;
    const float*  masb = mas  + (size_t)b * NATM;
    const int vbase = gx * V4PB;

    // ---------------- Phase 1: KE partial, fully coalesced ----------------
    // float4 at index L covers elements E=4L..4L+3; atom a = E/3, r = E%3 splits
    // the 4 squares between atoms a and a+1.
    float acc = 0.0f;
    #pragma unroll 4
    for (int k = 0; k < SSTG; k++) {           // staged half: also STS to smem
        const int L = vbase + k * TPB + t;
        float4 v = m[L];
        s_stage[k * TPB + t] = v;
        const unsigned E = 4u * (unsigned)L;
        const unsigned a = __umulhi(E, 0xAAAAAAABu) >> 1;   // E/3
        const unsigned r = E - 3u * a;                      // E%3
        float p  = v.x * v.x, q  = v.y * v.y;
        float u  = v.z * v.z, w2 = v.w * v.w;
        float cA = p, cB = w2;
        if (r < 2u)  cA += q; else cB += q;
        if (r == 0u) cA += u; else cB += u;
        acc += __fdividef(cA, masb[a]) + __fdividef(cB, masb[a + 1]);
    }
    #pragma unroll 4
    for (int k = SSTG; k < V4PT; k++) {        // plain half
        const int L = vbase + k * TPB + t;
        float4 v = m[L];
        const unsigned E = 4u * (unsigned)L;
        const unsigned a = __umulhi(E, 0xAAAAAAABu) >> 1;
        const unsigned r = E - 3u * a;
        float p  = v.x * v.x, q  = v.y * v.y;
        float u  = v.z * v.z, w2 = v.w * v.w;
        float cA = p, cB = w2;
        if (r < 2u)  cA += q; else cB += q;
        if (r == 0u) cA += u; else cB += u;
        acc += __fdividef(cA, masb[a]) + __fdividef(cB, masb[a + 1]);
    }

    // warp reduce (float), then cross-warp in double
    #pragma unroll
    for (int off = 16; off > 0; off >>= 1)
        acc += __shfl_down_sync(0xffffffffu, acc, off);

    __shared__ double s_warp[TPB / 32];
    __shared__ float  s_scale;
    const int wid = t >> 5, lid = t & 31;
    if (lid == 0) s_warp[wid] = (double)acc;
    __syncthreads();

    if (t == 0) {
        double tot = 0.0;
        #pragma unroll
        for (int i = 0; i < TPB / 32; i++) tot += s_warp[i];
        g_part[b * GX + gx] = tot;
        __threadfence();

        // ---------------- Grid sync (ticketed, replay-safe) ----------------
        unsigned int ticket = atomicAdd(&g_bar, 1u);
        unsigned int target = (ticket / NBLK + 1u) * NBLK;
        while (*((volatile unsigned int*)&g_bar) < target) __nanosleep(32);
        __threadfence();

        // ---------------- Phase 2: chain math for batch b ----------------
        double ked = 0.0;
        #pragma unroll
        for (int i = 0; i < GX; i++) ked += g_part[b * GX + i];

        const float wts[7] = {
            0.78451361047756f, 0.235573213359357f, -1.17767998417887f,
            (float)(1.0 - 2.0 * (0.78451361047756 + 0.235573213359357 - 1.17767998417887)),
            -1.17767998417887f, 0.235573213359357f, 0.78451361047756f
        };

        const double kgd = (double)kbt[b] * (double)(NATM * DDIM);
        const float  kbT = kbt[b];
        const float  dts = dtm[b] * (stp_p[0] / (float)NRESPA_);

        float pn[CCH], mn[CCH], imq[CCH];
        #pragma unroll
        for (int c = 0; c < CCH; c++) {
            pn[c]  = pos_nhc[b * CCH + c];
            mn[c]  = mom_nhc[b * CCH + c];
            imq[c] = 1.0f / mas_nhc[b * CCH + c];
        }

        double cum = 1.0;
        for (int r = 0; r < NRESPA_; r++) {
            #pragma unroll
            for (int iw = 0; iw < 7; iw++) {
                const float dea  = dts * wts[iw];
                const float dea2 = dea * 0.5f;
                const float dea4 = dea * 0.25f;

                float g[CCH], mc[CCH];
                g[0] = (float)(ked - kgd);
                #pragma unroll
                for (int j = 1; j < CCH; j++)
                    g[j] = mn[j - 1] * mn[j - 1] * imq[j - 1] - kbT;

                #pragma unroll
                for (int c = 0; c < CCH; c++) mc[c] = mn[c];
                mc[CCH - 1] += g[CCH - 1] * dea2;

                #pragma unroll
                for (int j = CCH - 2; j >= 0; j--) {
                    float f = __expf(-mc[j + 1] * imq[j + 1] * dea4);
                    mc[j] = (mc[j] * f + g[j] * dea2) * f;
                }

                #pragma unroll
                for (int c = 0; c < CCH; c++) pn[c] += mc[c] * imq[c] * dea;

                const float s = __expf(-mc[0] * imq[0] * dea);
                cum *= (double)s;
                ked *= (double)s * (double)s;

                g[0] = (float)(ked - kgd);
                #pragma unroll
                for (int j = CCH - 2; j >= 0; j--) {
                    float f = __expf(-mc[j + 1] * imq[j + 1] * dea4);
                    mc[j] = (mc[j] * f + g[j] * dea2) * f;
                }
                mc[CCH - 1] += g[CCH - 1] * dea2;

                #pragma unroll
                for (int c = 0; c < CCH; c++) mn[c] = mc[c];
            }
        }

        s_scale = (float)cum;
        if (gx == 0) {
            #pragma unroll
            for (int c = 0; c < CCH; c++) {
                out_posnhc[b * CCH + c] = pn[c];
                out_momnhc[b * CCH + c] = mn[c];
            }
        }
    }
    __syncthreads();

    // ------- Phase 3: rescale. First half from smem (on-chip, immediate), --
    // ------- second half from L2-hot global lines. Streaming stores. -------
    const float s = s_scale;
    float4* o = out_mom4 + (size_t)b * NVEC;
    #pragma unroll 4
    for (int k = 0; k < SSTG; k++) {
        float4 v = s_stage[k * TPB + t];
        v.x *= s; v.y *= s; v.z *= s; v.w *= s;
        st_stream(o + vbase + k * TPB + t, v);
    }
    #pragma unroll 4
    for (int k = SSTG; k < V4PT; k++) {
        const int L = vbase + k * TPB + t;
        float4 v = m[L];
        v.x *= s; v.y *= s; v.z *= s; v.w *= s;
        st_stream(o + L, v);
    }
}

// ---------------------------------------------------------------------------
extern "C" void kernel_launch(void* const* d_in, const int* in_sizes, int n_in,
                              void* d_out, int out_size) {
    // inputs: 0 pos, 1 mom, 2 mas, 3 kbt, 4 dtm, 5 pos_nhc, 6 mom_nhc, 7 mas_nhc, 8 stp
    const float* mom     = (const float*)d_in[1];
    const float* mas     = (const float*)d_in[2];
    const float* kbt     = (const float*)d_in[3];
    const float* dtm     = (const float*)d_in[4];
    const float* pos_nhc = (const float*)d_in[5];
    const float* mom_nhc = (const float*)d_in[6];
    const float* mas_nhc = (const float*)d_in[7];
    const float* stp     = (const float*)d_in[8];

    float* out = (float*)d_out;
    float* out_mom    = out;                          // [B, N, D]
    float* out_posnhc = out + (size_t)BB * NPER;      // [B, C]
    float* out_momnhc = out_posnhc + BB * CCH;        // [B, C]

    static int attr_done = 0;
    if (!attr_done) {
        cudaFuncSetAttribute(nhc_fused_kernel,
                             cudaFuncAttributeMaxDynamicSharedMemorySize,
                             SMEM_DYN);
        attr_done = 1;
    }

    dim3 grid(GX, BB);                                // 128 blocks, 1 per SM
    nhc_fused_kernel<<<grid, TPB, SMEM_DYN>>>(
        (const float4*)mom, mas,
        kbt, dtm, pos_nhc, mom_nhc, mas_nhc, stp,
        (float4*)out_mom, out_posnhc, out_momnhc);
}